// round 4
// baseline (speedup 1.0000x reference)
#include <cuda_runtime.h>
#include <cmath>

// Problem constants
#define B_    4096
#define IN_   1024
#define F_    512
#define HID_  128
#define D_    128
#define RH_   64
#define C_    10
#define R_    16
#define CH_   1280   // C_*HID_
#define NSEG_ 8
#define CHSEG_ 160   // CH_/NSEG_

// ---------------- device scratch ----------------
__device__ __align__(256) float g_w[R_][C_];
__device__ __align__(256) float g_rv[R_][D_];
__device__ __align__(256) float g_W2[R_][HID_];
__device__ __align__(256) float g_b1[R_][HID_];
__device__ __align__(256) float g_beff[R_];
__device__ __align__(256) float g_P[CH_][R_];          // P[ch][r] = w[r,c]*W2[r,h]
__device__ __align__(256) float g_WeffP[NSEG_][R_][F_];   // k_weff partials per ch-seg
__device__ __align__(256) float g_WeffBP[NSEG_][R_][F_];  // fc1_b partials per ch-seg
__device__ __align__(256) float g_Weff[R_][F_];        // summed (written by k_wx bx==0)
__device__ __align__(256) float g_WxPart[8][IN_][R_];
__device__ __align__(256) float g_WxT[IN_][R_];        // [i][r]
__device__ __align__(256) float g_cst[R_];

// ---------------- packed f32x2 helpers ----------------
__device__ __forceinline__ unsigned long long pk2(float a, float b) {
    unsigned long long r;
    asm("mov.b64 %0, {%1,%2};" : "=l"(r) : "f"(a), "f"(b));
    return r;
}
__device__ __forceinline__ void upk2(unsigned long long v, float& a, float& b) {
    asm("mov.b64 {%0,%1}, %2;" : "=f"(a), "=f"(b) : "l"(v));
}
#define FMA2(acc, a, b) asm("fma.rn.f32x2 %0, %1, %2, %0;" : "+l"(acc) : "l"(a), "l"(b))

// ============ k_rv: fused mixing weights w, r1, ray2v — block per r ============
__global__ void __launch_bounds__(256) k_rv(const float* __restrict__ pref,
                                            const float* __restrict__ wm1_w, const float* __restrict__ wm1_b,
                                            const float* __restrict__ wm2_w, const float* __restrict__ wm2_b,
                                            const float* __restrict__ ray0_w, const float* __restrict__ ray0_b,
                                            const float* __restrict__ ray2_w, const float* __restrict__ ray2_b) {
    int r = blockIdx.x;
    __shared__ float sh[16];
    __shared__ float sw[C_];
    __shared__ float sinv;
    __shared__ float sr1[RH_];
    __shared__ float sbias[D_];
    int t = threadIdx.x;
    float p0 = __ldg(pref + r * 2), p1 = __ldg(pref + r * 2 + 1);
    if (t < 16) {
        float a = p0 * __ldg(wm1_w + t * 2) + p1 * __ldg(wm1_w + t * 2 + 1) + __ldg(wm1_b + t);
        sh[t] = a > 0.f ? a : 0.f;
    }
    __syncthreads();
    if (t < C_) {
        float a = __ldg(wm2_b + t);
        #pragma unroll
        for (int j = 0; j < 16; j++) a += sh[j] * __ldg(wm2_w + t * 16 + j);
        sw[t] = 1.f / (1.f + expf(-a));
    }
    __syncthreads();
    if (t == 0) {
        float s = 0.f;
        #pragma unroll
        for (int c = 0; c < C_; c++) s += sw[c];
        sinv = 1.f / s;
    }
    __syncthreads();
    if (t < C_) {
        sw[t] *= sinv;
        g_w[r][t] = sw[t];
    }
    __syncthreads();
    if (t < RH_) {
        float a = 0.f;
        #pragma unroll
        for (int c = 0; c < C_; c++) {
            float2 rw = __ldg((const float2*)(ray0_w + (c * RH_ + t) * 2));
            a += sw[c] * (p0 * rw.x + p1 * rw.y + __ldg(ray0_b + c * RH_ + t));
        }
        sr1[t] = a > 0.f ? a : 0.f;
    }
    if (t >= 64 && t < 64 + D_) {
        int d = t - 64;
        float b = 0.f;
        #pragma unroll
        for (int c = 0; c < C_; c++) b += sw[c] * __ldg(ray2_b + c * D_ + d);
        sbias[d] = b;
    }
    __syncthreads();
    int warp = t >> 5, lane = t & 31;
    float r1a = sr1[lane], r1b = sr1[lane + 32];
    float acc[16];
    #pragma unroll
    for (int oi = 0; oi < 16; oi++) acc[oi] = 0.f;
    #pragma unroll
    for (int c = 0; c < C_; c++) {
        float wc = sw[c];
        #pragma unroll
        for (int oi = 0; oi < 16; oi++) {
            int o = warp * 16 + oi;
            const float* row = ray2_w + ((size_t)(c * D_ + o)) * RH_;
            acc[oi] += wc * (__ldg(row + lane) * r1a + __ldg(row + lane + 32) * r1b);
        }
    }
    #pragma unroll
    for (int oi = 0; oi < 16; oi++) {
        float s = acc[oi];
        #pragma unroll
        for (int off = 16; off > 0; off >>= 1) s += __shfl_down_sync(0xffffffffu, s, off);
        if (lane == 0) g_rv[r][warp * 16 + oi] = s + sbias[warp * 16 + oi];
    }
}

// ============ k_w2b1: W2[r,h] / b1[r,h] — block per (r,kind) ============
__global__ void __launch_bounds__(256) k_w2b1(const float* __restrict__ fc2_w,
                                              const float* __restrict__ fc2_b,
                                              const float* __restrict__ b1_w,
                                              const float* __restrict__ b1_b) {
    int r = blockIdx.x & 15, kind = blockIdx.x >> 4;
    const float* Wc = kind ? b1_w : fc2_w;
    const float* bc = kind ? b1_b : fc2_b;
    __shared__ float sw[C_];
    __shared__ float sbias[HID_];
    int t = threadIdx.x;
    if (t < C_) sw[t] = g_w[r][t];
    __syncthreads();
    if (t < HID_) {
        float b = 0.f;
        #pragma unroll
        for (int c = 0; c < C_; c++) b += sw[c] * __ldg(bc + c * HID_ + t);
        sbias[t] = b;
    }
    __syncthreads();
    int warp = t >> 5, lane = t & 31;
    float4 rv4 = *(const float4*)&g_rv[r][lane * 4];
    float acc[16];
    #pragma unroll
    for (int oi = 0; oi < 16; oi++) acc[oi] = 0.f;
    #pragma unroll
    for (int c = 0; c < C_; c++) {
        float wc = sw[c];
        #pragma unroll
        for (int oi = 0; oi < 16; oi++) {
            int o = warp * 16 + oi;
            float4 v = __ldg((const float4*)(Wc + ((size_t)(c * HID_ + o)) * D_) + lane);
            acc[oi] += wc * (v.x * rv4.x + v.y * rv4.y + v.z * rv4.z + v.w * rv4.w);
        }
    }
    #pragma unroll
    for (int oi = 0; oi < 16; oi++) {
        float s = acc[oi];
        #pragma unroll
        for (int off = 16; off > 0; off >>= 1) s += __shfl_down_sync(0xffffffffu, s, off);
        if (lane == 0) {
            int o = warp * 16 + oi;
            if (kind) g_b1[r][o] = s + sbias[o]; else g_W2[r][o] = s + sbias[o];
        }
    }
}

// ============ k_prep: beff (block 0) + P fill (16 blocks) ============
__global__ void k_prep(const float* __restrict__ b2_w, const float* __restrict__ b2_b) {
    int t = threadIdx.x;  // 512
    if (blockIdx.x == 0) {
        int warp = t >> 5, lane = t & 31;
        int r = warp;
        float4 rv4 = *(const float4*)&g_rv[r][lane * 4];
        float acc = 0.f;
        #pragma unroll
        for (int c = 0; c < C_; c++) {
            float wc = g_w[r][c];
            float4 bw = __ldg((const float4*)(b2_w + c * D_) + lane);
            acc += wc * (bw.x * rv4.x + bw.y * rv4.y + bw.z * rv4.z + bw.w * rv4.w);
            if (lane == 0) acc += wc * __ldg(b2_b + c);
        }
        float4 w24 = *(const float4*)&g_W2[r][lane * 4];
        float4 b14 = *(const float4*)&g_b1[r][lane * 4];
        acc += w24.x * b14.x + w24.y * b14.y + w24.z * b14.z + w24.w * b14.w;
        #pragma unroll
        for (int off = 16; off > 0; off >>= 1) acc += __shfl_down_sync(0xffffffffu, acc, off);
        if (lane == 0) g_beff[r] = acc;
    }
    int chbase = blockIdx.x * (CH_ / 16);
    for (int idx = t; idx < (CH_ / 16) * R_; idx += 512) {
        int ch = chbase + (idx >> 4), rr = idx & 15;
        g_P[ch][rr] = g_w[rr][ch >> 7] * g_W2[rr][ch & 127];
    }
}

// ============ k_weff_bias v2 (COALESCED): partials of fc1_b contribution ============
// grid (4 f-blocks, NSEG_ segs). lanes over f; loop over ch in segment.
__global__ void __launch_bounds__(128) k_weff_bias(const float* __restrict__ fc1_b) {
    int f = blockIdx.x * 128 + threadIdx.x;
    int seg = blockIdx.y;
    float acc[16];
    #pragma unroll
    for (int r = 0; r < 16; r++) acc[r] = 0.f;
    int ch0 = seg * CHSEG_;
    #pragma unroll 4
    for (int i = 0; i < CHSEG_; i++) {
        int ch = ch0 + i;
        float v = __ldg(fc1_b + (size_t)ch * 512u + f);
        const float4* pp = (const float4*)g_P[ch];
        float4 pA = __ldg(pp + 0), pB = __ldg(pp + 1), pC = __ldg(pp + 2), pD = __ldg(pp + 3);
        acc[0] += pA.x * v;  acc[1] += pA.y * v;  acc[2] += pA.z * v;  acc[3] += pA.w * v;
        acc[4] += pB.x * v;  acc[5] += pB.y * v;  acc[6] += pB.z * v;  acc[7] += pB.w * v;
        acc[8] += pC.x * v;  acc[9] += pC.y * v;  acc[10] += pC.z * v; acc[11] += pC.w * v;
        acc[12] += pD.x * v; acc[13] += pD.y * v; acc[14] += pD.z * v; acc[15] += pD.w * v;
    }
    #pragma unroll
    for (int r = 0; r < 16; r++) g_WeffBP[seg][r][f] = acc[r];
}

// ============ k_weff: stream fc1_w (335 MB) -> Weff partials ============
// grid (256 f-pairs, NSEG_ ch-segs). 128 thr = 4 warps: warp = chgrp*2 + dhalf.
// Each warp: 2 f values (share P loads), 2 d per lane, 80 ch, 4 ch/iter.
__global__ void __launch_bounds__(128, 3) k_weff(const float* __restrict__ fc1_w) {
    __shared__ __align__(16) float sP[CHSEG_][16];   // 10 KB
    __shared__ float sred[4][2][16];
    int seg = blockIdx.y;
    int f0 = blockIdx.x * 2;
    int t = threadIdx.x;
    int warp = t >> 5, lane = t & 31;
    int dhalf = warp & 1, chgrp = warp >> 1;

    for (int idx = t; idx < CHSEG_ * 16; idx += 128)
        ((float*)sP)[idx] = ((const float*)g_P[seg * CHSEG_])[idx];
    __syncthreads();

    const float* b0 = fc1_w + (size_t)(seg * CHSEG_) * 65536u
                    + (size_t)f0 * 128u + dhalf * 64 + lane * 2;
    unsigned long long acc0[16], acc1[16];
    #pragma unroll
    for (int k = 0; k < 16; k++) { acc0[k] = 0ull; acc1[k] = 0ull; }

    int chl0 = chgrp * (CHSEG_ / 2);
    for (int i = 0; i < CHSEG_ / 2; i += 4) {
        float2 v0[4], v1[4];
        #pragma unroll
        for (int q = 0; q < 4; q++) {
            size_t off = (size_t)(chl0 + i + q) * 65536u;
            v0[q] = __ldg((const float2*)(b0 + off));
            v1[q] = __ldg((const float2*)(b0 + off + 128));
        }
        #pragma unroll
        for (int q = 0; q < 4; q++) {
            int chl = chl0 + i + q;
            const ulonglong2* pp = (const ulonglong2*)sP[chl];
            ulonglong2 pA = pp[0], pB = pp[1], pC = pp[2], pD = pp[3];
            unsigned long long ux0 = pk2(v0[q].x, v0[q].x), uy0 = pk2(v0[q].y, v0[q].y);
            unsigned long long ux1 = pk2(v1[q].x, v1[q].x), uy1 = pk2(v1[q].y, v1[q].y);
            FMA2(acc0[0],  ux0, pA.x); FMA2(acc0[1],  uy0, pA.x);
            FMA2(acc0[2],  ux0, pA.y); FMA2(acc0[3],  uy0, pA.y);
            FMA2(acc0[4],  ux0, pB.x); FMA2(acc0[5],  uy0, pB.x);
            FMA2(acc0[6],  ux0, pB.y); FMA2(acc0[7],  uy0, pB.y);
            FMA2(acc0[8],  ux0, pC.x); FMA2(acc0[9],  uy0, pC.x);
            FMA2(acc0[10], ux0, pC.y); FMA2(acc0[11], uy0, pC.y);
            FMA2(acc0[12], ux0, pD.x); FMA2(acc0[13], uy0, pD.x);
            FMA2(acc0[14], ux0, pD.y); FMA2(acc0[15], uy0, pD.y);
            FMA2(acc1[0],  ux1, pA.x); FMA2(acc1[1],  uy1, pA.x);
            FMA2(acc1[2],  ux1, pA.y); FMA2(acc1[3],  uy1, pA.y);
            FMA2(acc1[4],  ux1, pB.x); FMA2(acc1[5],  uy1, pB.x);
            FMA2(acc1[6],  ux1, pB.y); FMA2(acc1[7],  uy1, pB.y);
            FMA2(acc1[8],  ux1, pC.x); FMA2(acc1[9],  uy1, pC.x);
            FMA2(acc1[10], ux1, pC.y); FMA2(acc1[11], uy1, pC.y);
            FMA2(acc1[12], ux1, pD.x); FMA2(acc1[13], uy1, pD.x);
            FMA2(acc1[14], ux1, pD.y); FMA2(acc1[15], uy1, pD.y);
        }
    }
    // epilogue: weight by rv[r][d], reduce lanes, then warps via smem
    int d0 = dhalf * 64 + lane * 2;
    float accr0[16], accr1[16];
    #pragma unroll
    for (int rp = 0; rp < 8; rp++) {
        #pragma unroll
        for (int j = 0; j < 2; j++) {
            float rva = g_rv[2 * rp][d0 + j], rvb = g_rv[2 * rp + 1][d0 + j];
            float a0, a1;
            upk2(acc0[rp * 2 + j], a0, a1);
            if (j == 0) { accr0[2 * rp] = a0 * rva; accr0[2 * rp + 1] = a1 * rvb; }
            else        { accr0[2 * rp] += a0 * rva; accr0[2 * rp + 1] += a1 * rvb; }
            upk2(acc1[rp * 2 + j], a0, a1);
            if (j == 0) { accr1[2 * rp] = a0 * rva; accr1[2 * rp + 1] = a1 * rvb; }
            else        { accr1[2 * rp] += a0 * rva; accr1[2 * rp + 1] += a1 * rvb; }
        }
    }
    #pragma unroll
    for (int off = 16; off > 0; off >>= 1) {
        #pragma unroll
        for (int r = 0; r < 16; r++) {
            accr0[r] += __shfl_down_sync(0xffffffffu, accr0[r], off);
            accr1[r] += __shfl_down_sync(0xffffffffu, accr1[r], off);
        }
    }
    if (lane == 0) {
        #pragma unroll
        for (int r = 0; r < 16; r++) {
            sred[warp][0][r] = accr0[r];
            sred[warp][1][r] = accr1[r];
        }
    }
    __syncthreads();
    if (t < 32) {
        int fi = t >> 4, r = t & 15;
        float s = sred[0][fi][r] + sred[1][fi][r] + sred[2][fi][r] + sred[3][fi][r];
        g_WeffP[seg][r][f0 + fi] = s;
    }
}

// ============ k_wx: reduce Weff partials + fold into base_w -> Wx partials ====
__global__ void __launch_bounds__(128) k_wx(const float* __restrict__ base_w) {
    __shared__ __align__(16) float sW[64][16];
    int i = blockIdx.x * 128 + threadIdx.x;
    int f0 = blockIdx.y * 64;
    for (int idx = threadIdx.x; idx < 64 * 16; idx += 128) {
        int ff = idx >> 4, r = idx & 15;
        float s = 0.f;
        #pragma unroll
        for (int sg = 0; sg < NSEG_; sg++)
            s += g_WeffP[sg][r][f0 + ff] + g_WeffBP[sg][r][f0 + ff];
        sW[ff][r] = s;
        if (blockIdx.x == 0) g_Weff[r][f0 + ff] = s;
    }
    __syncthreads();
    unsigned long long acc[8];
    #pragma unroll
    for (int rp = 0; rp < 8; rp++) acc[rp] = 0ull;
    #pragma unroll 4
    for (int ff = 0; ff < 64; ff++) {
        float bw = __ldg(base_w + (size_t)(f0 + ff) * IN_ + i);
        unsigned long long b2 = pk2(bw, bw);
        const unsigned long long* pw = (const unsigned long long*)sW[ff];
        #pragma unroll
        for (int rp = 0; rp < 8; rp++) {
            unsigned long long tt = pw[rp];
            FMA2(acc[rp], b2, tt);
        }
    }
    float* o = &g_WxPart[blockIdx.y][i][0];
    #pragma unroll
    for (int rp = 0; rp < 8; rp++) {
        float a, b; upk2(acc[rp], a, b);
        o[2 * rp] = a; o[2 * rp + 1] = b;
    }
}

// ============ k_wx_reduce: sum partials + cst[r] ============
__global__ void k_wx_reduce(const float* __restrict__ base_b) {
    int idx = blockIdx.x * 256 + threadIdx.x;
    if (idx < IN_ * R_) {
        int i = idx >> 4, r = idx & 15;
        float s = 0.f;
        #pragma unroll
        for (int p = 0; p < 8; p++) s += g_WxPart[p][i][r];
        g_WxT[i][r] = s;
    }
    if (blockIdx.x == 0) {
        int warp = threadIdx.x >> 5, lane = threadIdx.x & 31;
        #pragma unroll
        for (int rr = warp; rr < R_; rr += 8) {
            float a = 0.f;
            #pragma unroll
            for (int kk = 0; kk < 16; kk++) {
                int ff = kk * 32 + lane;
                a += g_Weff[rr][ff] * __ldg(base_b + ff);
            }
            #pragma unroll
            for (int off = 16; off > 0; off >>= 1) a += __shfl_down_sync(0xffffffffu, a, off);
            if (lane == 0) g_cst[rr] = g_beff[rr] + a;
        }
    }
}

// ============ k_out: out[r,b] = x[b]·Wx[r] + cst[r]; 2 b per warp ============
__global__ void __launch_bounds__(256) k_out(const float* __restrict__ x,
                                             float* __restrict__ out, int write_raw) {
    int warp = threadIdx.x >> 5, lane = threadIdx.x & 31;
    int b0 = (blockIdx.x * 8 + warp) * 2;
    unsigned long long acc[2][8];
    #pragma unroll
    for (int j = 0; j < 2; j++)
        #pragma unroll
        for (int rp = 0; rp < 8; rp++) acc[j][rp] = 0ull;

    #pragma unroll
    for (int k = 0; k < 8; k++) {
        float4 xv0 = __ldg((const float4*)(x + (size_t)(b0 + 0) * IN_) + k * 32 + lane);
        float4 xv1 = __ldg((const float4*)(x + (size_t)(b0 + 1) * IN_) + k * 32 + lane);
        int ib = (k * 32 + lane) * 4;
        #pragma unroll
        for (int di = 0; di < 4; di++) {
            const ulonglong2* wr = (const ulonglong2*)g_WxT[ib + di];
            ulonglong2 wA = __ldg(wr + 0), wB = __ldg(wr + 1);
            ulonglong2 wC = __ldg(wr + 2), wD = __ldg(wr + 3);
            float x0c = di == 0 ? xv0.x : di == 1 ? xv0.y : di == 2 ? xv0.z : xv0.w;
            float x1c = di == 0 ? xv1.x : di == 1 ? xv1.y : di == 2 ? xv1.z : xv1.w;
            unsigned long long u0 = pk2(x0c, x0c), u1 = pk2(x1c, x1c);
            FMA2(acc[0][0], u0, wA.x); FMA2(acc[0][1], u0, wA.y);
            FMA2(acc[0][2], u0, wB.x); FMA2(acc[0][3], u0, wB.y);
            FMA2(acc[0][4], u0, wC.x); FMA2(acc[0][5], u0, wC.y);
            FMA2(acc[0][6], u0, wD.x); FMA2(acc[0][7], u0, wD.y);
            FMA2(acc[1][0], u1, wA.x); FMA2(acc[1][1], u1, wA.y);
            FMA2(acc[1][2], u1, wB.x); FMA2(acc[1][3], u1, wB.y);
            FMA2(acc[1][4], u1, wC.x); FMA2(acc[1][5], u1, wC.y);
            FMA2(acc[1][6], u1, wD.x); FMA2(acc[1][7], u1, wD.y);
        }
    }
    float accr[2][16];
    #pragma unroll
    for (int j = 0; j < 2; j++)
        #pragma unroll
        for (int rp = 0; rp < 8; rp++) upk2(acc[j][rp], accr[j][2 * rp], accr[j][2 * rp + 1]);
    #pragma unroll
    for (int off = 16; off > 0; off >>= 1)
        #pragma unroll
        for (int j = 0; j < 2; j++)
            #pragma unroll
            for (int r = 0; r < 16; r++)
                accr[j][r] += __shfl_down_sync(0xffffffffu, accr[j][r], off);
    if (lane == 0) {
        #pragma unroll
        for (int j = 0; j < 2; j++) {
            #pragma unroll
            for (int r = 0; r < 16; r++) {
                float v = accr[j][r] + g_cst[r];
                out[r * B_ + b0 + j] = 1.f / (1.f + expf(-v));
                if (write_raw) out[R_ * B_ + r * B_ + b0 + j] = v;
            }
        }
    }
}

// ---------------- launcher ----------------
extern "C" void kernel_launch(void* const* d_in, const int* in_sizes, int n_in,
                              void* d_out, int out_size) {
    const float* x      = (const float*)d_in[0];
    const float* pref   = (const float*)d_in[1];
    const float* base_w = (const float*)d_in[2];
    const float* base_b = (const float*)d_in[3];
    const float* wm1_w  = (const float*)d_in[4];
    const float* wm1_b  = (const float*)d_in[5];
    const float* wm2_w  = (const float*)d_in[6];
    const float* wm2_b  = (const float*)d_in[7];
    const float* ray0_w = (const float*)d_in[8];
    const float* ray0_b = (const float*)d_in[9];
    const float* ray2_w = (const float*)d_in[10];
    const float* ray2_b = (const float*)d_in[11];
    const float* fc1_w  = (const float*)d_in[12];
    const float* fc1_b  = (const float*)d_in[13];
    const float* b1_w   = (const float*)d_in[14];
    const float* b1_b   = (const float*)d_in[15];
    const float* fc2_w  = (const float*)d_in[16];
    const float* fc2_b  = (const float*)d_in[17];
    const float* b2_w   = (const float*)d_in[18];
    const float* b2_b   = (const float*)d_in[19];
    float* out = (float*)d_out;
    int write_raw = (out_size >= 2 * R_ * B_) ? 1 : 0;

    k_rv<<<R_, 256>>>(pref, wm1_w, wm1_b, wm2_w, wm2_b,
                      ray0_w, ray0_b, ray2_w, ray2_b);
    k_w2b1<<<32, 256>>>(fc2_w, fc2_b, b1_w, b1_b);
    k_prep<<<16, 512>>>(b2_w, b2_b);
    k_weff_bias<<<dim3(4, NSEG_), 128>>>(fc1_b);
    k_weff<<<dim3(F_ / 2, NSEG_), 128>>>(fc1_w);
    k_wx<<<dim3(8, 8), 128>>>(base_w);
    k_wx_reduce<<<64, 256>>>(base_b);
    k_out<<<B_ / 16, 256>>>(x, out, write_raw);
}

// round 5
// speedup vs baseline: 1.3222x; 1.3222x over previous
#include <cuda_runtime.h>
#include <cmath>

// Problem constants
#define B_    4096
#define IN_   1024
#define F_    512
#define HID_  128
#define D_    128
#define RH_   64
#define C_    10
#define R_    16
#define CH_   1280   // C_*HID_
#define NSEG_ 8
#define CHSEG_ 160   // CH_/NSEG_
#define BSEG_ 40
#define BCH_  32     // CH_/BSEG_

// ---------------- device scratch ----------------
__device__ __align__(256) float g_w[R_][C_];
__device__ __align__(256) float g_rv[R_][D_];
__device__ __align__(256) float g_W2[R_][HID_];
__device__ __align__(256) float g_b1[R_][HID_];
__device__ __align__(256) float g_beff[R_];
__device__ __align__(256) float g_P[CH_][R_];            // P[ch][r] = w[r,c]*W2[r,h]
__device__ __align__(256) float g_WeffP[NSEG_][R_][F_];  // k_weff partials per ch-seg
__device__ __align__(256) float g_WeffBP[BSEG_][R_][F_]; // fc1_b partials per ch-seg
__device__ __align__(256) float g_Weff[R_][F_];
__device__ __align__(256) float g_WxPart[8][IN_][R_];
__device__ __align__(256) float g_WxT[IN_][R_];          // [i][r]
__device__ __align__(256) float g_cst[R_];

// ---------------- packed f32x2 helpers ----------------
__device__ __forceinline__ unsigned long long pk2(float a, float b) {
    unsigned long long r;
    asm("mov.b64 %0, {%1,%2};" : "=l"(r) : "f"(a), "f"(b));
    return r;
}
__device__ __forceinline__ void upk2(unsigned long long v, float& a, float& b) {
    asm("mov.b64 {%0,%1}, %2;" : "=f"(a), "=f"(b) : "l"(v));
}
#define FMA2(acc, a, b) asm("fma.rn.f32x2 %0, %1, %2, %0;" : "+l"(acc) : "l"(a), "l"(b))

// ============ k_rv: fused mixing weights w, r1, ray2v — block per r ============
__global__ void __launch_bounds__(256) k_rv(const float* __restrict__ pref,
                                            const float* __restrict__ wm1_w, const float* __restrict__ wm1_b,
                                            const float* __restrict__ wm2_w, const float* __restrict__ wm2_b,
                                            const float* __restrict__ ray0_w, const float* __restrict__ ray0_b,
                                            const float* __restrict__ ray2_w, const float* __restrict__ ray2_b) {
    int r = blockIdx.x;
    __shared__ float sh[16];
    __shared__ float sw[C_];
    __shared__ float sinv;
    __shared__ float sr1[RH_];
    __shared__ float sbias[D_];
    int t = threadIdx.x;
    float p0 = __ldg(pref + r * 2), p1 = __ldg(pref + r * 2 + 1);
    if (t < 16) {
        float a = p0 * __ldg(wm1_w + t * 2) + p1 * __ldg(wm1_w + t * 2 + 1) + __ldg(wm1_b + t);
        sh[t] = a > 0.f ? a : 0.f;
    }
    __syncthreads();
    if (t < C_) {
        float a = __ldg(wm2_b + t);
        #pragma unroll
        for (int j = 0; j < 16; j++) a += sh[j] * __ldg(wm2_w + t * 16 + j);
        sw[t] = 1.f / (1.f + expf(-a));
    }
    __syncthreads();
    if (t == 0) {
        float s = 0.f;
        #pragma unroll
        for (int c = 0; c < C_; c++) s += sw[c];
        sinv = 1.f / s;
    }
    __syncthreads();
    if (t < C_) {
        sw[t] *= sinv;
        g_w[r][t] = sw[t];
    }
    __syncthreads();
    if (t < RH_) {
        float a = 0.f;
        #pragma unroll
        for (int c = 0; c < C_; c++) {
            float2 rw = __ldg((const float2*)(ray0_w + (c * RH_ + t) * 2));
            a += sw[c] * (p0 * rw.x + p1 * rw.y + __ldg(ray0_b + c * RH_ + t));
        }
        sr1[t] = a > 0.f ? a : 0.f;
    }
    if (t >= 64 && t < 64 + D_) {
        int d = t - 64;
        float b = 0.f;
        #pragma unroll
        for (int c = 0; c < C_; c++) b += sw[c] * __ldg(ray2_b + c * D_ + d);
        sbias[d] = b;
    }
    __syncthreads();
    int warp = t >> 5, lane = t & 31;
    float r1a = sr1[lane], r1b = sr1[lane + 32];
    float acc[16];
    #pragma unroll
    for (int oi = 0; oi < 16; oi++) acc[oi] = 0.f;
    #pragma unroll
    for (int c = 0; c < C_; c++) {
        float wc = sw[c];
        #pragma unroll
        for (int oi = 0; oi < 16; oi++) {
            int o = warp * 16 + oi;
            const float* row = ray2_w + ((size_t)(c * D_ + o)) * RH_;
            acc[oi] += wc * (__ldg(row + lane) * r1a + __ldg(row + lane + 32) * r1b);
        }
    }
    #pragma unroll
    for (int oi = 0; oi < 16; oi++) {
        float s = acc[oi];
        #pragma unroll
        for (int off = 16; off > 0; off >>= 1) s += __shfl_down_sync(0xffffffffu, s, off);
        if (lane == 0) g_rv[r][warp * 16 + oi] = s + sbias[warp * 16 + oi];
    }
}

// ============ k_w2b1: W2[r,h] / b1[r,h] — block per (r,kind) ============
__global__ void __launch_bounds__(256) k_w2b1(const float* __restrict__ fc2_w,
                                              const float* __restrict__ fc2_b,
                                              const float* __restrict__ b1_w,
                                              const float* __restrict__ b1_b) {
    int r = blockIdx.x & 15, kind = blockIdx.x >> 4;
    const float* Wc = kind ? b1_w : fc2_w;
    const float* bc = kind ? b1_b : fc2_b;
    __shared__ float sw[C_];
    __shared__ float sbias[HID_];
    int t = threadIdx.x;
    if (t < C_) sw[t] = g_w[r][t];
    __syncthreads();
    if (t < HID_) {
        float b = 0.f;
        #pragma unroll
        for (int c = 0; c < C_; c++) b += sw[c] * __ldg(bc + c * HID_ + t);
        sbias[t] = b;
    }
    __syncthreads();
    int warp = t >> 5, lane = t & 31;
    float4 rv4 = *(const float4*)&g_rv[r][lane * 4];
    float acc[16];
    #pragma unroll
    for (int oi = 0; oi < 16; oi++) acc[oi] = 0.f;
    #pragma unroll
    for (int c = 0; c < C_; c++) {
        float wc = sw[c];
        #pragma unroll
        for (int oi = 0; oi < 16; oi++) {
            int o = warp * 16 + oi;
            float4 v = __ldg((const float4*)(Wc + ((size_t)(c * HID_ + o)) * D_) + lane);
            acc[oi] += wc * (v.x * rv4.x + v.y * rv4.y + v.z * rv4.z + v.w * rv4.w);
        }
    }
    #pragma unroll
    for (int oi = 0; oi < 16; oi++) {
        float s = acc[oi];
        #pragma unroll
        for (int off = 16; off > 0; off >>= 1) s += __shfl_down_sync(0xffffffffu, s, off);
        if (lane == 0) {
            int o = warp * 16 + oi;
            if (kind) g_b1[r][o] = s + sbias[o]; else g_W2[r][o] = s + sbias[o];
        }
    }
}

// ============ k_prep: beff (block 0) + P fill (16 blocks) ============
__global__ void k_prep(const float* __restrict__ b2_w, const float* __restrict__ b2_b) {
    int t = threadIdx.x;  // 512
    if (blockIdx.x == 0) {
        int warp = t >> 5, lane = t & 31;
        int r = warp;
        float4 rv4 = *(const float4*)&g_rv[r][lane * 4];
        float acc = 0.f;
        #pragma unroll
        for (int c = 0; c < C_; c++) {
            float wc = g_w[r][c];
            float4 bw = __ldg((const float4*)(b2_w + c * D_) + lane);
            acc += wc * (bw.x * rv4.x + bw.y * rv4.y + bw.z * rv4.z + bw.w * rv4.w);
            if (lane == 0) acc += wc * __ldg(b2_b + c);
        }
        float4 w24 = *(const float4*)&g_W2[r][lane * 4];
        float4 b14 = *(const float4*)&g_b1[r][lane * 4];
        acc += w24.x * b14.x + w24.y * b14.y + w24.z * b14.z + w24.w * b14.w;
        #pragma unroll
        for (int off = 16; off > 0; off >>= 1) acc += __shfl_down_sync(0xffffffffu, acc, off);
        if (lane == 0) g_beff[r] = acc;
    }
    int chbase = blockIdx.x * (CH_ / 16);
    for (int idx = t; idx < (CH_ / 16) * R_; idx += 512) {
        int ch = chbase + (idx >> 4), rr = idx & 15;
        g_P[ch][rr] = g_w[rr][ch >> 7] * g_W2[rr][ch & 127];
    }
}

// ============ k_weff: stream fc1_w (335 MB) -> Weff partials ============
// grid (64 f-groups, NSEG_ ch-segs); 256 thr = 8 warps. Warp owns ONE f and the
// whole 160-ch segment; lane owns 4 d's (float4 loads -> 2 KB in flight/warp
// with 4-ch prefetch). acc = 32 u64 packed over r-pairs. P tile in smem.
__global__ void __launch_bounds__(256, 2) k_weff(const float* __restrict__ fc1_w) {
    __shared__ __align__(16) float sP[CHSEG_][16];   // 10 KB
    int seg = blockIdx.y;
    int t = threadIdx.x;
    int warp = t >> 5, lane = t & 31;
    int f = blockIdx.x * 8 + warp;

    for (int idx = t; idx < CHSEG_ * 16; idx += 256)
        ((float*)sP)[idx] = ((const float*)g_P[seg * CHSEG_])[idx];
    __syncthreads();

    const float4* base = (const float4*)(fc1_w
        + (size_t)(seg * CHSEG_) * 65536u + (size_t)f * 128u) + lane;
    // ch stride in float4 units: 65536/4 = 16384

    unsigned long long acc[4][8];
    #pragma unroll
    for (int j = 0; j < 4; j++)
        #pragma unroll
        for (int rp = 0; rp < 8; rp++) acc[j][rp] = 0ull;

    float4 v[4], vn[4];
    #pragma unroll
    for (int q = 0; q < 4; q++) v[q] = __ldg(base + q * 16384);

    for (int cb = 0; cb < CHSEG_; cb += 4) {
        if (cb + 4 < CHSEG_) {
            #pragma unroll
            for (int q = 0; q < 4; q++)
                vn[q] = __ldg(base + (cb + 4 + q) * 16384);
        }
        #pragma unroll
        for (int q = 0; q < 4; q++) {
            int ch = cb + q;
            const ulonglong2* pp = (const ulonglong2*)sP[ch];
            ulonglong2 pA = pp[0], pB = pp[1], pC = pp[2], pD = pp[3];
            unsigned long long u0 = pk2(v[q].x, v[q].x);
            unsigned long long u1 = pk2(v[q].y, v[q].y);
            unsigned long long u2 = pk2(v[q].z, v[q].z);
            unsigned long long u3 = pk2(v[q].w, v[q].w);
            FMA2(acc[0][0], u0, pA.x); FMA2(acc[0][1], u0, pA.y);
            FMA2(acc[0][2], u0, pB.x); FMA2(acc[0][3], u0, pB.y);
            FMA2(acc[0][4], u0, pC.x); FMA2(acc[0][5], u0, pC.y);
            FMA2(acc[0][6], u0, pD.x); FMA2(acc[0][7], u0, pD.y);
            FMA2(acc[1][0], u1, pA.x); FMA2(acc[1][1], u1, pA.y);
            FMA2(acc[1][2], u1, pB.x); FMA2(acc[1][3], u1, pB.y);
            FMA2(acc[1][4], u1, pC.x); FMA2(acc[1][5], u1, pC.y);
            FMA2(acc[1][6], u1, pD.x); FMA2(acc[1][7], u1, pD.y);
            FMA2(acc[2][0], u2, pA.x); FMA2(acc[2][1], u2, pA.y);
            FMA2(acc[2][2], u2, pB.x); FMA2(acc[2][3], u2, pB.y);
            FMA2(acc[2][4], u2, pC.x); FMA2(acc[2][5], u2, pC.y);
            FMA2(acc[2][6], u2, pD.x); FMA2(acc[2][7], u2, pD.y);
            FMA2(acc[3][0], u3, pA.x); FMA2(acc[3][1], u3, pA.y);
            FMA2(acc[3][2], u3, pB.x); FMA2(acc[3][3], u3, pB.y);
            FMA2(acc[3][4], u3, pC.x); FMA2(acc[3][5], u3, pC.y);
            FMA2(acc[3][6], u3, pD.x); FMA2(acc[3][7], u3, pD.y);
        }
        #pragma unroll
        for (int q = 0; q < 4; q++) v[q] = vn[q];
    }

    // epilogue: weight by rv[r][d], reduce over lanes (d), lane0 writes partial
    int d0 = lane * 4;
    float accr[16];
    #pragma unroll
    for (int r = 0; r < 16; r++) accr[r] = 0.f;
    #pragma unroll
    for (int j = 0; j < 4; j++) {
        #pragma unroll
        for (int rp = 0; rp < 8; rp++) {
            float a0, a1; upk2(acc[j][rp], a0, a1);
            accr[2 * rp]     += a0 * g_rv[2 * rp][d0 + j];
            accr[2 * rp + 1] += a1 * g_rv[2 * rp + 1][d0 + j];
        }
    }
    #pragma unroll
    for (int off = 16; off > 0; off >>= 1)
        #pragma unroll
        for (int r = 0; r < 16; r++)
            accr[r] += __shfl_down_sync(0xffffffffu, accr[r], off);
    if (lane == 0) {
        #pragma unroll
        for (int r = 0; r < 16; r++) g_WeffP[seg][r][f] = accr[r];
    }
}

// ============ k_weff_bias: fc1_b partials, grid (4, BSEG_) ============
__global__ void __launch_bounds__(128) k_weff_bias(const float* __restrict__ fc1_b) {
    int f = blockIdx.x * 128 + threadIdx.x;
    int seg = blockIdx.y;
    float acc[16];
    #pragma unroll
    for (int r = 0; r < 16; r++) acc[r] = 0.f;
    int ch0 = seg * BCH_;
    #pragma unroll 8
    for (int i = 0; i < BCH_; i++) {
        int ch = ch0 + i;
        float v = __ldg(fc1_b + (size_t)ch * 512u + f);
        const float4* pp = (const float4*)g_P[ch];
        float4 pA = __ldg(pp + 0), pB = __ldg(pp + 1), pC = __ldg(pp + 2), pD = __ldg(pp + 3);
        acc[0] += pA.x * v;  acc[1] += pA.y * v;  acc[2] += pA.z * v;  acc[3] += pA.w * v;
        acc[4] += pB.x * v;  acc[5] += pB.y * v;  acc[6] += pB.z * v;  acc[7] += pB.w * v;
        acc[8] += pC.x * v;  acc[9] += pC.y * v;  acc[10] += pC.z * v; acc[11] += pC.w * v;
        acc[12] += pD.x * v; acc[13] += pD.y * v; acc[14] += pD.z * v; acc[15] += pD.w * v;
    }
    #pragma unroll
    for (int r = 0; r < 16; r++) g_WeffBP[seg][r][f] = acc[r];
}

// ============ k_wsum: fold all partials into g_Weff ============
__global__ void k_wsum() {
    int idx = blockIdx.x * 256 + threadIdx.x;  // 32 blocks x 256 = 8192 = R_*F_
    int r = idx >> 9, f = idx & 511;
    float s = 0.f;
    #pragma unroll
    for (int sg = 0; sg < NSEG_; sg++) s += g_WeffP[sg][r][f];
    #pragma unroll
    for (int sg = 0; sg < BSEG_; sg++) s += g_WeffBP[sg][r][f];
    g_Weff[r][f] = s;
}

// ============ k_wx: fold Weff into base_w -> Wx partials ============
__global__ void __launch_bounds__(128) k_wx(const float* __restrict__ base_w) {
    __shared__ __align__(16) float sW[64][16];
    int i = blockIdx.x * 128 + threadIdx.x;
    int f0 = blockIdx.y * 64;
    for (int idx = threadIdx.x; idx < 64 * 16; idx += 128) {
        int ff = idx >> 4, r = idx & 15;
        sW[ff][r] = g_Weff[r][f0 + ff];
    }
    __syncthreads();
    unsigned long long acc[8];
    #pragma unroll
    for (int rp = 0; rp < 8; rp++) acc[rp] = 0ull;
    #pragma unroll 4
    for (int ff = 0; ff < 64; ff++) {
        float bw = __ldg(base_w + (size_t)(f0 + ff) * IN_ + i);
        unsigned long long b2 = pk2(bw, bw);
        const unsigned long long* pw = (const unsigned long long*)sW[ff];
        #pragma unroll
        for (int rp = 0; rp < 8; rp++) {
            unsigned long long tt = pw[rp];
            FMA2(acc[rp], b2, tt);
        }
    }
    float* o = &g_WxPart[blockIdx.y][i][0];
    #pragma unroll
    for (int rp = 0; rp < 8; rp++) {
        float a, b; upk2(acc[rp], a, b);
        o[2 * rp] = a; o[2 * rp + 1] = b;
    }
}

// ============ k_wx_reduce: sum partials + cst[r] ============
__global__ void k_wx_reduce(const float* __restrict__ base_b) {
    int idx = blockIdx.x * 256 + threadIdx.x;
    if (idx < IN_ * R_) {
        int i = idx >> 4, r = idx & 15;
        float s = 0.f;
        #pragma unroll
        for (int p = 0; p < 8; p++) s += g_WxPart[p][i][r];
        g_WxT[i][r] = s;
    }
    if (blockIdx.x == 0) {
        int warp = threadIdx.x >> 5, lane = threadIdx.x & 31;
        #pragma unroll
        for (int rr = warp; rr < R_; rr += 8) {
            float a = 0.f;
            #pragma unroll
            for (int kk = 0; kk < 16; kk++) {
                int ff = kk * 32 + lane;
                a += g_Weff[rr][ff] * __ldg(base_b + ff);
            }
            #pragma unroll
            for (int off = 16; off > 0; off >>= 1) a += __shfl_down_sync(0xffffffffu, a, off);
            if (lane == 0) g_cst[rr] = g_beff[rr] + a;
        }
    }
}

// ============ k_out: out[r,b] = x[b]·Wx[r] + cst[r]; 2 b per warp ============
__global__ void __launch_bounds__(256) k_out(const float* __restrict__ x,
                                             float* __restrict__ out, int write_raw) {
    int warp = threadIdx.x >> 5, lane = threadIdx.x & 31;
    int b0 = (blockIdx.x * 8 + warp) * 2;
    unsigned long long acc[2][8];
    #pragma unroll
    for (int j = 0; j < 2; j++)
        #pragma unroll
        for (int rp = 0; rp < 8; rp++) acc[j][rp] = 0ull;

    #pragma unroll
    for (int k = 0; k < 8; k++) {
        float4 xv0 = __ldg((const float4*)(x + (size_t)(b0 + 0) * IN_) + k * 32 + lane);
        float4 xv1 = __ldg((const float4*)(x + (size_t)(b0 + 1) * IN_) + k * 32 + lane);
        int ib = (k * 32 + lane) * 4;
        #pragma unroll
        for (int di = 0; di < 4; di++) {
            const ulonglong2* wr = (const ulonglong2*)g_WxT[ib + di];
            ulonglong2 wA = __ldg(wr + 0), wB = __ldg(wr + 1);
            ulonglong2 wC = __ldg(wr + 2), wD = __ldg(wr + 3);
            float x0c = di == 0 ? xv0.x : di == 1 ? xv0.y : di == 2 ? xv0.z : xv0.w;
            float x1c = di == 0 ? xv1.x : di == 1 ? xv1.y : di == 2 ? xv1.z : xv1.w;
            unsigned long long u0 = pk2(x0c, x0c), u1 = pk2(x1c, x1c);
            FMA2(acc[0][0], u0, wA.x); FMA2(acc[0][1], u0, wA.y);
            FMA2(acc[0][2], u0, wB.x); FMA2(acc[0][3], u0, wB.y);
            FMA2(acc[0][4], u0, wC.x); FMA2(acc[0][5], u0, wC.y);
            FMA2(acc[0][6], u0, wD.x); FMA2(acc[0][7], u0, wD.y);
            FMA2(acc[1][0], u1, wA.x); FMA2(acc[1][1], u1, wA.y);
            FMA2(acc[1][2], u1, wB.x); FMA2(acc[1][3], u1, wB.y);
            FMA2(acc[1][4], u1, wC.x); FMA2(acc[1][5], u1, wC.y);
            FMA2(acc[1][6], u1, wD.x); FMA2(acc[1][7], u1, wD.y);
        }
    }
    float accr[2][16];
    #pragma unroll
    for (int j = 0; j < 2; j++)
        #pragma unroll
        for (int rp = 0; rp < 8; rp++) upk2(acc[j][rp], accr[j][2 * rp], accr[j][2 * rp + 1]);
    #pragma unroll
    for (int off = 16; off > 0; off >>= 1)
        #pragma unroll
        for (int j = 0; j < 2; j++)
            #pragma unroll
            for (int r = 0; r < 16; r++)
                accr[j][r] += __shfl_down_sync(0xffffffffu, accr[j][r], off);
    if (lane == 0) {
        #pragma unroll
        for (int j = 0; j < 2; j++) {
            #pragma unroll
            for (int r = 0; r < 16; r++) {
                float v = accr[j][r] + g_cst[r];
                out[r * B_ + b0 + j] = 1.f / (1.f + expf(-v));
                if (write_raw) out[R_ * B_ + r * B_ + b0 + j] = v;
            }
        }
    }
}

// ---------------- launcher ----------------
extern "C" void kernel_launch(void* const* d_in, const int* in_sizes, int n_in,
                              void* d_out, int out_size) {
    const float* x      = (const float*)d_in[0];
    const float* pref   = (const float*)d_in[1];
    const float* base_w = (const float*)d_in[2];
    const float* base_b = (const float*)d_in[3];
    const float* wm1_w  = (const float*)d_in[4];
    const float* wm1_b  = (const float*)d_in[5];
    const float* wm2_w  = (const float*)d_in[6];
    const float* wm2_b  = (const float*)d_in[7];
    const float* ray0_w = (const float*)d_in[8];
    const float* ray0_b = (const float*)d_in[9];
    const float* ray2_w = (const float*)d_in[10];
    const float* ray2_b = (const float*)d_in[11];
    const float* fc1_w  = (const float*)d_in[12];
    const float* fc1_b  = (const float*)d_in[13];
    const float* b1_w   = (const float*)d_in[14];
    const float* b1_b   = (const float*)d_in[15];
    const float* fc2_w  = (const float*)d_in[16];
    const float* fc2_b  = (const float*)d_in[17];
    const float* b2_w   = (const float*)d_in[18];
    const float* b2_b   = (const float*)d_in[19];
    float* out = (float*)d_out;
    int write_raw = (out_size >= 2 * R_ * B_) ? 1 : 0;

    k_rv<<<R_, 256>>>(pref, wm1_w, wm1_b, wm2_w, wm2_b,
                      ray0_w, ray0_b, ray2_w, ray2_b);
    k_w2b1<<<32, 256>>>(fc2_w, fc2_b, b1_w, b1_b);
    k_prep<<<16, 512>>>(b2_w, b2_b);
    k_weff<<<dim3(F_ / 8, NSEG_), 256>>>(fc1_w);      // launch #4 -> gets profiled
    k_weff_bias<<<dim3(4, BSEG_), 128>>>(fc1_b);
    k_wsum<<<32, 256>>>();
    k_wx<<<dim3(8, 8), 128>>>(base_w);
    k_wx_reduce<<<64, 256>>>(base_b);
    k_out<<<B_ / 16, 256>>>(x, out, write_raw);
}